// round 10
// baseline (speedup 1.0000x reference)
#include <cuda_runtime.h>
#include <cstdint>

// ---------------------------------------------------------------------------
// MultiHeadSelfAttention:
//   1) qkv = x @ qkv_w^T + qkv_b    mma.sync tf32x3 (R7-proven GEMM)
//   2) flash attention               mma.sync tf32x3, 16-row warp tiles
//   3) out = ctx @ out_w^T + out_b   mma.sync tf32x3 (R7-proven GEMM)
// ---------------------------------------------------------------------------

#define D_EMBED 1024
#define N_HEADS 16
#define D_HEAD  64
#define N_B     2
#define N_T     2048
#define M_TOT   (N_B * N_T)      // 4096
#define N_QKV   (3 * D_EMBED)    // 3072
#define K_DIM   1024

__device__ float g_qkv[(size_t)M_TOT * N_QKV];   // 48 MB
__device__ float g_ctx[(size_t)M_TOT * D_EMBED]; // 16 MB

// ---------------------------------------------------------------------------
// tf32 + fast-exp helpers
// ---------------------------------------------------------------------------
__device__ __forceinline__ uint32_t f2tf(float x) {
    uint32_t r;
    asm("cvt.rna.tf32.f32 %0, %1;" : "=r"(r) : "f"(x));
    return r;
}

__device__ __forceinline__ void cvt_split(float x, uint32_t& hi, uint32_t& lo) {
    hi = f2tf(x);
    lo = f2tf(x - __uint_as_float(hi));
}

__device__ __forceinline__ uint2 split2(float x) {
    uint32_t h = f2tf(x);
    uint32_t l = f2tf(x - __uint_as_float(h));
    return make_uint2(h, l);
}

__device__ __forceinline__ void mma_tf32(float* d, const uint32_t* a,
                                         const uint32_t* b) {
    asm volatile(
        "mma.sync.aligned.m16n8k8.row.col.f32.tf32.tf32.f32 "
        "{%0,%1,%2,%3}, {%4,%5,%6,%7}, {%8,%9}, {%0,%1,%2,%3};"
        : "+f"(d[0]), "+f"(d[1]), "+f"(d[2]), "+f"(d[3])
        : "r"(a[0]), "r"(a[1]), "r"(a[2]), "r"(a[3]), "r"(b[0]), "r"(b[1]));
}

// exp(x) for x <= 0 via 2^t with degree-5 poly; no MUFU. rel err ~1e-7.
__device__ __forceinline__ float fexp(float x) {
    float t = x * 1.4426950408889634f;
    t = fmaxf(t, -126.0f);
    float fi = floorf(t);
    float f = t - fi;
    float p = 1.33336498402e-3f;
    p = fmaf(p, f, 9.81094791730e-3f);
    p = fmaf(p, f, 5.55041086648e-2f);
    p = fmaf(p, f, 2.40226506959e-1f);
    p = fmaf(p, f, 6.93147180560e-1f);
    p = fmaf(p, f, 1.0f);
    return __int_as_float(((int)fi + 127) << 23) * p;
}

// ---------------------------------------------------------------------------
// GEMM (verbatim R7-passing): C[m][n] = sum_k A[m][k]*W[n][k] + bias[n]
// CTA 128x128, warps 2(M)x4(N), warp tile 64x32, K-tile 16, pitch 20.
// ---------------------------------------------------------------------------
#define TKK 16
#define PIT 20

__device__ __forceinline__ void mma_gemm_body(
    const float* __restrict__ A, const float* __restrict__ W,
    const float* __restrict__ bias, float* __restrict__ C, int N)
{
    __shared__ float As[2][128][PIT];
    __shared__ float Ws[2][128][PIT];

    const int t    = threadIdx.x;
    const int lane = t & 31;
    const int w    = t >> 5;
    const int wm   = w & 1;
    const int wn   = w >> 1;
    const int g    = lane >> 2;
    const int tg   = lane & 3;
    const int m0   = blockIdx.y * 128;
    const int n0   = blockIdx.x * 128;

    const int lr = t >> 1;
    const int lk = (t & 1) * 8;
    const float* Ag = A + (size_t)(m0 + lr) * K_DIM + lk;
    const float* Wg = W + (size_t)(n0 + lr) * K_DIM + lk;

    float acc[4][4][4];
    #pragma unroll
    for (int i = 0; i < 4; i++)
        #pragma unroll
        for (int j = 0; j < 4; j++)
            #pragma unroll
            for (int e = 0; e < 4; e++) acc[i][j][e] = 0.f;

    {
        float4 a0 = *(const float4*)(Ag);
        float4 a1 = *(const float4*)(Ag + 4);
        float4 w0 = *(const float4*)(Wg);
        float4 w1 = *(const float4*)(Wg + 4);
        *(float4*)&As[0][lr][lk]     = a0;
        *(float4*)&As[0][lr][lk + 4] = a1;
        *(float4*)&Ws[0][lr][lk]     = w0;
        *(float4*)&Ws[0][lr][lk + 4] = w1;
    }
    __syncthreads();

    int cur = 0;
    for (int kt = 0; kt < K_DIM / TKK; kt++) {
        const bool more = (kt + 1 < K_DIM / TKK);
        float4 pa0, pa1, pw0, pw1;
        if (more) {
            const float* Ap = Ag + (kt + 1) * TKK;
            const float* Wp = Wg + (kt + 1) * TKK;
            pa0 = *(const float4*)(Ap);
            pa1 = *(const float4*)(Ap + 4);
            pw0 = *(const float4*)(Wp);
            pw1 = *(const float4*)(Wp + 4);
        }

        #pragma unroll
        for (int s = 0; s < 2; s++) {
            const int ks = s * 8;
            uint32_t Ah[4][4], Al[4][4], Bh[4][2], Bl[4][2];
            #pragma unroll
            for (int mf = 0; mf < 4; mf++) {
                const int rb = wm * 64 + mf * 16;
                cvt_split(As[cur][rb + g][ks + tg],         Ah[mf][0], Al[mf][0]);
                cvt_split(As[cur][rb + g + 8][ks + tg],     Ah[mf][1], Al[mf][1]);
                cvt_split(As[cur][rb + g][ks + tg + 4],     Ah[mf][2], Al[mf][2]);
                cvt_split(As[cur][rb + g + 8][ks + tg + 4], Ah[mf][3], Al[mf][3]);
            }
            #pragma unroll
            for (int nf = 0; nf < 4; nf++) {
                const int nb = wn * 32 + nf * 8;
                cvt_split(Ws[cur][nb + g][ks + tg],     Bh[nf][0], Bl[nf][0]);
                cvt_split(Ws[cur][nb + g][ks + tg + 4], Bh[nf][1], Bl[nf][1]);
            }
            #pragma unroll
            for (int mf = 0; mf < 4; mf++)
                #pragma unroll
                for (int nf = 0; nf < 4; nf++) {
                    mma_tf32(acc[mf][nf], Ah[mf], Bh[nf]);
                    mma_tf32(acc[mf][nf], Ah[mf], Bl[nf]);
                    mma_tf32(acc[mf][nf], Al[mf], Bh[nf]);
                }
        }

        if (more) {
            const int nxt = cur ^ 1;
            *(float4*)&As[nxt][lr][lk]     = pa0;
            *(float4*)&As[nxt][lr][lk + 4] = pa1;
            *(float4*)&Ws[nxt][lr][lk]     = pw0;
            *(float4*)&Ws[nxt][lr][lk + 4] = pw1;
            __syncthreads();
            cur = nxt;
        }
    }

    #pragma unroll
    for (int mf = 0; mf < 4; mf++) {
        const int r = m0 + wm * 64 + mf * 16 + g;
        #pragma unroll
        for (int nf = 0; nf < 4; nf++) {
            const int c = n0 + wn * 32 + nf * 8 + 2 * tg;
            const float b0 = bias[c], b1 = bias[c + 1];
            float2 v0 = make_float2(acc[mf][nf][0] + b0, acc[mf][nf][1] + b1);
            float2 v1 = make_float2(acc[mf][nf][2] + b0, acc[mf][nf][3] + b1);
            *(float2*)(C + (size_t)r * N + c)       = v0;
            *(float2*)(C + (size_t)(r + 8) * N + c) = v1;
        }
    }
}

__global__ __launch_bounds__(256, 1)
void gemm_qkv_kernel(const float* __restrict__ x,
                     const float* __restrict__ w,
                     const float* __restrict__ b)
{
    mma_gemm_body(x, w, b, g_qkv, N_QKV);
}

__global__ __launch_bounds__(256, 1)
void gemm_out_kernel(const float* __restrict__ w,
                     const float* __restrict__ b,
                     float* __restrict__ out)
{
    mma_gemm_body(g_ctx, w, b, out, D_EMBED);
}

// ---------------------------------------------------------------------------
// Flash attention on HMMA (fixed warp layout): CTA = (b, h, 128-row Q tile),
// 8 warps x 16 COMPLETE rows each — every warp sees all 64 keys of its rows,
// so online-softmax stats are complete per warp (the R8 bug).
// Q/P fp32 in smem (split at fragment load); K and V^T pre-split packed
// uint2.  tf32x3 for S=QK^T and O+=PV.  Poly-exp (no MUFU).
// ---------------------------------------------------------------------------
#define QP  68
#define KP2 66
#define FL_SMEM (2 * 128 * QP * 4 + 2 * 64 * KP2 * 8)  // 137216 B

__global__ __launch_bounds__(256, 1)
void flash_kernel()
{
    extern __shared__ char fsmraw[];
    float* Qs  = (float*)fsmraw;            // [128][QP]  q-major
    float* Ps  = Qs + 128 * QP;             // [128][QP]  q-major (cols=key)
    uint2* K2  = (uint2*)(Ps + 128 * QP);   // [64 key][KP2] (col=d)
    uint2* Vt2 = K2 + 64 * KP2;             // [64 d][KP2]   (col=key^swz)

    const int b  = blockIdx.z;
    const int h  = blockIdx.y;
    const int q0 = blockIdx.x * 128;
    const int t  = threadIdx.x;
    const int lane = t & 31;
    const int w  = t >> 5;
    const int rw = w * 16;      // this warp's 16 rows
    const int g  = lane >> 2;
    const int tg = lane & 3;

    // ---- load Q tile, scaled, fp32 ----
    {
        const int qr = t >> 1;
        const int dh = (t & 1) * 32;
        const float* qg = g_qkv + (size_t)(b * N_T + q0 + qr) * N_QKV
                        + h * D_HEAD + dh;
        #pragma unroll
        for (int u = 0; u < 8; u++) {
            float4 v = *(const float4*)(qg + u * 4);
            float* p = Qs + qr * QP + dh + u * 4;
            p[0] = v.x * 0.125f; p[1] = v.y * 0.125f;
            p[2] = v.z * 0.125f; p[3] = v.w * 0.125f;
        }
    }

    float mi[2], li[2], o[8][4];
    mi[0] = mi[1] = -1e30f;
    li[0] = li[1] = 0.f;
    #pragma unroll
    for (int nf = 0; nf < 8; nf++)
        #pragma unroll
        for (int e = 0; e < 4; e++) o[nf][e] = 0.f;

    for (int kt = 0; kt < N_T / 64; kt++) {
        __syncthreads();   // prev PV done reading K2/Vt2/Ps; Q visible (kt==0)

        // ---- load K (natural) and V^T (swizzled), split to packed uint2 ----
        {
            const int kr = t & 63;            // key row
            const int dh = (t >> 6) * 16;     // 16-d slab
            const float* kg = g_qkv + (size_t)(b * N_T + kt * 64 + kr) * N_QKV
                            + D_EMBED + h * D_HEAD + dh;
            const float* vg = kg + D_EMBED;
            #pragma unroll
            for (int u = 0; u < 4; u++) {
                float4 kv = *(const float4*)(kg + u * 4);
                float4 vv = *(const float4*)(vg + u * 4);
                const int d0 = dh + u * 4;
                uint2* kp = K2 + kr * KP2 + d0;
                kp[0] = split2(kv.x); kp[1] = split2(kv.y);
                kp[2] = split2(kv.z); kp[3] = split2(kv.w);
                float ve[4] = {vv.x, vv.y, vv.z, vv.w};
                #pragma unroll
                for (int e = 0; e < 4; e++) {
                    const int d = d0 + e;
                    const int col = kr ^ (((d >> 4) & 3) << 3);
                    Vt2[d * KP2 + col] = split2(ve[e]);
                }
            }
        }
        __syncthreads();

        // ---- S = Q K^T : warp tile 16 rows x 64 keys, tf32 x3 ----
        float s[8][4];
        #pragma unroll
        for (int nf = 0; nf < 8; nf++)
            #pragma unroll
            for (int e = 0; e < 4; e++) s[nf][e] = 0.f;

        #pragma unroll
        for (int k8 = 0; k8 < 8; k8++) {
            const int ks = k8 * 8;
            uint32_t Ah[4], Al[4];
            cvt_split(Qs[(rw + g) * QP + ks + tg],         Ah[0], Al[0]);
            cvt_split(Qs[(rw + g + 8) * QP + ks + tg],     Ah[1], Al[1]);
            cvt_split(Qs[(rw + g) * QP + ks + tg + 4],     Ah[2], Al[2]);
            cvt_split(Qs[(rw + g + 8) * QP + ks + tg + 4], Ah[3], Al[3]);
            #pragma unroll
            for (int nf = 0; nf < 8; nf++) {
                const int key = nf * 8 + g;
                uint2 b0 = K2[key * KP2 + ks + tg];
                uint2 b1 = K2[key * KP2 + ks + tg + 4];
                uint32_t Bh[2] = {b0.x, b1.x};
                uint32_t Bl[2] = {b0.y, b1.y};
                mma_tf32(s[nf], Ah, Bh);
                mma_tf32(s[nf], Ah, Bl);
                mma_tf32(s[nf], Al, Bh);
            }
        }

        // ---- online softmax: rows g (e0,e1) and g+8 (e2,e3), full 64 keys ----
        #pragma unroll
        for (int hh = 0; hh < 2; hh++) {
            const int e0 = 2 * hh;
            float mt = -1e30f;
            #pragma unroll
            for (int nf = 0; nf < 8; nf++)
                mt = fmaxf(mt, fmaxf(s[nf][e0], s[nf][e0 + 1]));
            mt = fmaxf(mt, __shfl_xor_sync(0xffffffffu, mt, 1));
            mt = fmaxf(mt, __shfl_xor_sync(0xffffffffu, mt, 2));
            const float mnew = fmaxf(mi[hh], mt);
            const float al   = fexp(mi[hh] - mnew);
            float ls = 0.f;
            #pragma unroll
            for (int nf = 0; nf < 8; nf++) {
                float e1 = fexp(s[nf][e0] - mnew);
                float e2 = fexp(s[nf][e0 + 1] - mnew);
                s[nf][e0] = e1; s[nf][e0 + 1] = e2;
                ls += e1 + e2;
            }
            ls += __shfl_xor_sync(0xffffffffu, ls, 1);
            ls += __shfl_xor_sync(0xffffffffu, ls, 2);
            li[hh] = li[hh] * al + ls;
            mi[hh] = mnew;
            #pragma unroll
            for (int nf = 0; nf < 8; nf++) {
                o[nf][e0]     *= al;
                o[nf][e0 + 1] *= al;
            }
        }

        // ---- write P rows (fp32, this warp's own 16 rows, all 64 keys) ----
        #pragma unroll
        for (int nf = 0; nf < 8; nf++) {
            const int c = nf * 8 + 2 * tg;
            *(float2*)&Ps[(rw + g) * QP + c]     = make_float2(s[nf][0], s[nf][1]);
            *(float2*)&Ps[(rw + g + 8) * QP + c] = make_float2(s[nf][2], s[nf][3]);
        }
        __syncthreads();

        // ---- O += P V : warp tile 16 rows x 64 d, tf32 x3 ----
        #pragma unroll
        for (int k8 = 0; k8 < 8; k8++) {
            const int ks = k8 * 8;
            uint32_t Ph[4], Pl[4];
            cvt_split(Ps[(rw + g) * QP + ks + tg],         Ph[0], Pl[0]);
            cvt_split(Ps[(rw + g + 8) * QP + ks + tg],     Ph[1], Pl[1]);
            cvt_split(Ps[(rw + g) * QP + ks + tg + 4],     Ph[2], Pl[2]);
            cvt_split(Ps[(rw + g + 8) * QP + ks + tg + 4], Ph[3], Pl[3]);
            #pragma unroll
            for (int nf = 0; nf < 8; nf++) {
                const int dd = nf * 8 + g;
                const int m  = ((dd >> 4) & 3) << 3;
                uint2 b0 = Vt2[dd * KP2 + ((ks + tg) ^ m)];
                uint2 b1 = Vt2[dd * KP2 + ((ks + tg + 4) ^ m)];
                uint32_t Bh[2] = {b0.x, b1.x};
                uint32_t Bl[2] = {b0.y, b1.y};
                mma_tf32(o[nf], Ph, Bh);
                mma_tf32(o[nf], Ph, Bl);
                mma_tf32(o[nf], Pl, Bh);
            }
        }
    }

    // ---- epilogue ----
    {
        const float i0 = 1.f / li[0];
        const float i1 = 1.f / li[1];
        const int r0 = b * N_T + q0 + rw + g;
        #pragma unroll
        for (int nf = 0; nf < 8; nf++) {
            const int c = h * D_HEAD + nf * 8 + 2 * tg;
            *(float2*)(g_ctx + (size_t)r0 * D_EMBED + c) =
                make_float2(o[nf][0] * i0, o[nf][1] * i0);
            *(float2*)(g_ctx + (size_t)(r0 + 8) * D_EMBED + c) =
                make_float2(o[nf][2] * i1, o[nf][3] * i1);
        }
    }
}

// ---------------------------------------------------------------------------
extern "C" void kernel_launch(void* const* d_in, const int* in_sizes, int n_in,
                              void* d_out, int out_size)
{
    (void)in_sizes; (void)n_in; (void)out_size;
    const float* x     = (const float*)d_in[0];
    const float* qkv_w = (const float*)d_in[1];
    const float* qkv_b = (const float*)d_in[2];
    const float* out_w = (const float*)d_in[3];
    const float* out_b = (const float*)d_in[4];
    float* out = (float*)d_out;

    cudaFuncSetAttribute(flash_kernel,
                         cudaFuncAttributeMaxDynamicSharedMemorySize, FL_SMEM);

    gemm_qkv_kernel<<<dim3(N_QKV / 128, M_TOT / 128), 256>>>(x, qkv_w, qkv_b);

    flash_kernel<<<dim3(N_T / 128, N_HEADS, N_B), 256, FL_SMEM>>>();

    gemm_out_kernel<<<dim3(D_EMBED / 128, M_TOT / 128), 256>>>(out_w, out_b, out);
}

// round 11
// speedup vs baseline: 1.6983x; 1.6983x over previous
#include <cuda_runtime.h>
#include <cstdint>

// ---------------------------------------------------------------------------
// MultiHeadSelfAttention, all-HMMA bf16x3 (m16n8k16, fp32-grade accuracy):
//   1) qkv = x @ qkv_w^T + qkv_b     bf16x3, packed hi/lo smem
//   2) flash attention                bf16x3 S and PV, P stays in registers
//   3) out = ctx @ out_w^T + out_b    bf16x3
// ---------------------------------------------------------------------------

#define D_EMBED 1024
#define N_HEADS 16
#define D_HEAD  64
#define N_B     2
#define N_T     2048
#define M_TOT   (N_B * N_T)      // 4096
#define N_QKV   (3 * D_EMBED)    // 3072
#define K_DIM   1024

__device__ float g_qkv[(size_t)M_TOT * N_QKV];   // 48 MB
__device__ float g_ctx[(size_t)M_TOT * D_EMBED]; // 16 MB

// ---------------------------------------------------------------------------
// bf16 split helpers + fast exp
// ---------------------------------------------------------------------------
// pack two floats as bf16x2; first arg lands in the LOW half (k-smaller elem)
__device__ __forceinline__ uint32_t pkbf(float lo, float hi) {
    uint32_t r;
    asm("cvt.rn.bf16x2.f32 %0, %1, %2;" : "=r"(r) : "f"(hi), "f"(lo));
    return r;
}

// split a pair (x0, x1) into (hi-pack, lo-pack); hi+lo == x to ~16 mantissa bits
__device__ __forceinline__ uint2 splitp(float x0, float x1) {
    uint32_t h = pkbf(x0, x1);
    float r0 = x0 - __uint_as_float(h << 16);
    float r1 = x1 - __uint_as_float(h & 0xffff0000u);
    return make_uint2(h, pkbf(r0, r1));
}

__device__ __forceinline__ void mma_bf16(float* d, const uint32_t* a,
                                         const uint32_t* b) {
    asm volatile(
        "mma.sync.aligned.m16n8k16.row.col.f32.bf16.bf16.f32 "
        "{%0,%1,%2,%3}, {%4,%5,%6,%7}, {%8,%9}, {%0,%1,%2,%3};"
        : "+f"(d[0]), "+f"(d[1]), "+f"(d[2]), "+f"(d[3])
        : "r"(a[0]), "r"(a[1]), "r"(a[2]), "r"(a[3]), "r"(b[0]), "r"(b[1]));
}

// exp(x) for x <= 0 via 2^t with degree-5 poly; no MUFU. rel err ~1e-7.
__device__ __forceinline__ float fexp(float x) {
    float t = x * 1.4426950408889634f;
    t = fmaxf(t, -126.0f);
    float fi = floorf(t);
    float f = t - fi;
    float p = 1.33336498402e-3f;
    p = fmaf(p, f, 9.81094791730e-3f);
    p = fmaf(p, f, 5.55041086648e-2f);
    p = fmaf(p, f, 2.40226506959e-1f);
    p = fmaf(p, f, 6.93147180560e-1f);
    p = fmaf(p, f, 1.0f);
    return __int_as_float(((int)fi + 127) << 23) * p;
}

// ---------------------------------------------------------------------------
// GEMM: C[m][n] = sum_k A[m][k]*W[n][k] + bias[n]
// CTA 128x128, warps 2(M)x4(N), warp tile 64x32, K-tile 16 (one k16 step),
// double-buffered smem of packed (hi,lo) bf16-pair uint2 (split at store).
// Pitch 12 uint2 -> conflict-free fragment LDS.64.
// ---------------------------------------------------------------------------
#define GP2   12
#define GSMEM (2 * 2 * 128 * GP2 * 8)   // 49152 B dynamic

__device__ __forceinline__ void mma_gemm_body(
    const float* __restrict__ A, const float* __restrict__ W,
    const float* __restrict__ bias, float* __restrict__ C, int N)
{
    extern __shared__ uint2 gs2[];
    uint2* As2 = gs2;                    // [2][128][GP2]
    uint2* Ws2 = gs2 + 2 * 128 * GP2;

    const int t    = threadIdx.x;
    const int lane = t & 31;
    const int w    = t >> 5;
    const int wm   = w & 1;
    const int wn   = w >> 1;
    const int g    = lane >> 2;
    const int tg   = lane & 3;
    const int m0   = blockIdx.y * 128;
    const int n0   = blockIdx.x * 128;

    const int lr  = t >> 1;          // tile row 0..127
    const int lk2 = (t & 1) * 4;     // kpair offset 0 or 4
    const float* Ag = A + (size_t)(m0 + lr) * K_DIM + lk2 * 2;
    const float* Wg = W + (size_t)(n0 + lr) * K_DIM + lk2 * 2;

    float acc[4][4][4];
    #pragma unroll
    for (int i = 0; i < 4; i++)
        #pragma unroll
        for (int j = 0; j < 4; j++)
            #pragma unroll
            for (int e = 0; e < 4; e++) acc[i][j][e] = 0.f;

    // prologue: stage 0
    {
        float4 a0 = *(const float4*)(Ag);
        float4 a1 = *(const float4*)(Ag + 4);
        float4 w0 = *(const float4*)(Wg);
        float4 w1 = *(const float4*)(Wg + 4);
        uint2* Ap = As2 + lr * GP2 + lk2;
        uint2* Wp = Ws2 + lr * GP2 + lk2;
        Ap[0] = splitp(a0.x, a0.y); Ap[1] = splitp(a0.z, a0.w);
        Ap[2] = splitp(a1.x, a1.y); Ap[3] = splitp(a1.z, a1.w);
        Wp[0] = splitp(w0.x, w0.y); Wp[1] = splitp(w0.z, w0.w);
        Wp[2] = splitp(w1.x, w1.y); Wp[3] = splitp(w1.z, w1.w);
    }
    __syncthreads();

    int cur = 0;
    for (int kt = 0; kt < K_DIM / 16; kt++) {
        const bool more = (kt + 1 < K_DIM / 16);
        float4 pa0, pa1, pw0, pw1;
        if (more) {
            const float* Ap = Ag + (kt + 1) * 16;
            const float* Wp = Wg + (kt + 1) * 16;
            pa0 = *(const float4*)(Ap);
            pa1 = *(const float4*)(Ap + 4);
            pw0 = *(const float4*)(Wp);
            pw1 = *(const float4*)(Wp + 4);
        }

        const uint2* Ab = As2 + cur * 128 * GP2;
        const uint2* Wb = Ws2 + cur * 128 * GP2;

        uint2 af[4][4];
        #pragma unroll
        for (int mf = 0; mf < 4; mf++) {
            const int rb = wm * 64 + mf * 16;
            af[mf][0] = Ab[(rb + g) * GP2 + tg];
            af[mf][1] = Ab[(rb + g + 8) * GP2 + tg];
            af[mf][2] = Ab[(rb + g) * GP2 + tg + 4];
            af[mf][3] = Ab[(rb + g + 8) * GP2 + tg + 4];
        }
        uint2 bf2[4][2];
        #pragma unroll
        for (int nf = 0; nf < 4; nf++) {
            const int nb = wn * 32 + nf * 8;
            bf2[nf][0] = Wb[(nb + g) * GP2 + tg];
            bf2[nf][1] = Wb[(nb + g) * GP2 + tg + 4];
        }
        #pragma unroll
        for (int mf = 0; mf < 4; mf++) {
            uint32_t Ah[4] = {af[mf][0].x, af[mf][1].x, af[mf][2].x, af[mf][3].x};
            uint32_t Al[4] = {af[mf][0].y, af[mf][1].y, af[mf][2].y, af[mf][3].y};
            #pragma unroll
            for (int nf = 0; nf < 4; nf++) {
                uint32_t Bh[2] = {bf2[nf][0].x, bf2[nf][1].x};
                uint32_t Bl[2] = {bf2[nf][0].y, bf2[nf][1].y};
                mma_bf16(acc[mf][nf], Ah, Bh);
                mma_bf16(acc[mf][nf], Ah, Bl);
                mma_bf16(acc[mf][nf], Al, Bh);
            }
        }

        if (more) {
            const int nxt = cur ^ 1;
            uint2* Ap = As2 + nxt * 128 * GP2 + lr * GP2 + lk2;
            uint2* Wp = Ws2 + nxt * 128 * GP2 + lr * GP2 + lk2;
            Ap[0] = splitp(pa0.x, pa0.y); Ap[1] = splitp(pa0.z, pa0.w);
            Ap[2] = splitp(pa1.x, pa1.y); Ap[3] = splitp(pa1.z, pa1.w);
            Wp[0] = splitp(pw0.x, pw0.y); Wp[1] = splitp(pw0.z, pw0.w);
            Wp[2] = splitp(pw1.x, pw1.y); Wp[3] = splitp(pw1.z, pw1.w);
            __syncthreads();
            cur = nxt;
        }
    }

    #pragma unroll
    for (int mf = 0; mf < 4; mf++) {
        const int r = m0 + wm * 64 + mf * 16 + g;
        #pragma unroll
        for (int nf = 0; nf < 4; nf++) {
            const int c = n0 + wn * 32 + nf * 8 + 2 * tg;
            const float b0 = bias[c], b1 = bias[c + 1];
            float2 v0 = make_float2(acc[mf][nf][0] + b0, acc[mf][nf][1] + b1);
            float2 v1 = make_float2(acc[mf][nf][2] + b0, acc[mf][nf][3] + b1);
            *(float2*)(C + (size_t)r * N + c)       = v0;
            *(float2*)(C + (size_t)(r + 8) * N + c) = v1;
        }
    }
}

__global__ __launch_bounds__(256, 1)
void gemm_qkv_kernel(const float* __restrict__ x,
                     const float* __restrict__ w,
                     const float* __restrict__ b)
{
    mma_gemm_body(x, w, b, g_qkv, N_QKV);
}

__global__ __launch_bounds__(256, 1)
void gemm_out_kernel(const float* __restrict__ w,
                     const float* __restrict__ b,
                     float* __restrict__ out)
{
    mma_gemm_body(g_ctx, w, b, out, D_EMBED);
}

// ---------------------------------------------------------------------------
// Flash attention, bf16x3 m16n8k16: CTA = (b, h, 128-row Q tile), 8 warps x
// 16 complete rows (full-key softmax per warp).  Q/K/V pre-split packed
// uint2 in smem; P formed register-to-register from S accumulators (no smem
// round-trip, 2 barriers/tile).  K store uses per-key XOR-4 swizzle so the
// 32-key store pattern is conflict-free.
// ---------------------------------------------------------------------------
#define QP2  36
#define KPF  36
#define FL_SMEM ((128 * QP2 + 2 * 64 * KPF) * 8)   // 73728 B

__global__ __launch_bounds__(256, 2)
void flash_kernel()
{
    extern __shared__ uint2 fs2[];
    uint2* Q2 = fs2;                 // [128][QP2]  row=q, col=d-pair
    uint2* K2 = Q2 + 128 * QP2;      // [64][KPF]   row=key, col=d-pair^swz
    uint2* V2 = K2 + 64 * KPF;       // [64][KPF]   row=d,  col=key-pair

    const int b  = blockIdx.z;
    const int h  = blockIdx.y;
    const int q0 = blockIdx.x * 128;
    const int t  = threadIdx.x;
    const int lane = t & 31;
    const int w  = t >> 5;
    const int rw = w * 16;      // this warp's 16 rows
    const int g  = lane >> 2;
    const int tg = lane & 3;

    // ---- load Q tile, scale, split, pack ----
    {
        const int qr = t >> 1;
        const int dh = (t & 1) * 32;
        const float* qg = g_qkv + (size_t)(b * N_T + q0 + qr) * N_QKV
                        + h * D_HEAD + dh;
        uint2* qp = Q2 + qr * QP2 + dh / 2;
        #pragma unroll
        for (int u = 0; u < 8; u++) {
            float4 v = *(const float4*)(qg + u * 4);
            qp[2 * u]     = splitp(v.x * 0.125f, v.y * 0.125f);
            qp[2 * u + 1] = splitp(v.z * 0.125f, v.w * 0.125f);
        }
    }

    float mi[2], li[2], o[8][4];
    mi[0] = mi[1] = -1e30f;
    li[0] = li[1] = 0.f;
    #pragma unroll
    for (int nf = 0; nf < 8; nf++)
        #pragma unroll
        for (int e = 0; e < 4; e++) o[nf][e] = 0.f;

    for (int kt = 0; kt < N_T / 64; kt++) {
        __syncthreads();   // prev tile done reading K2/V2; Q2 visible (kt==0)

        // ---- K: thread owns (key, 16-d slab); XOR-4 swizzle per key ----
        {
            const int key = t & 63;
            const int d0  = (t >> 6) * 16;
            const int swz = ((key >> 3) & 1) * 4;
            const float* kg = g_qkv + (size_t)(b * N_T + kt * 64 + key) * N_QKV
                            + D_EMBED + h * D_HEAD + d0;
            uint2* kp = K2 + key * KPF;
            const int p0 = d0 / 2;
            #pragma unroll
            for (int u = 0; u < 4; u++) {
                float4 kv = *(const float4*)(kg + u * 4);
                kp[(p0 + 2 * u) ^ swz]     = splitp(kv.x, kv.y);
                kp[(p0 + 2 * u + 1) ^ swz] = splitp(kv.z, kv.w);
            }
        }
        // ---- V: thread owns (key-pair, 8-d slab); packs (even,odd) keys ----
        {
            const int kp  = t & 31;
            const int d0  = (t >> 5) * 8;
            const float* vg0 = g_qkv + (size_t)(b * N_T + kt * 64 + 2 * kp) * N_QKV
                             + 2 * D_EMBED + h * D_HEAD + d0;
            const float* vg1 = vg0 + N_QKV;
            float4 x0 = *(const float4*)(vg0);
            float4 x1 = *(const float4*)(vg0 + 4);
            float4 y0 = *(const float4*)(vg1);
            float4 y1 = *(const float4*)(vg1 + 4);
            V2[(d0 + 0) * KPF + kp] = splitp(x0.x, y0.x);
            V2[(d0 + 1) * KPF + kp] = splitp(x0.y, y0.y);
            V2[(d0 + 2) * KPF + kp] = splitp(x0.z, y0.z);
            V2[(d0 + 3) * KPF + kp] = splitp(x0.w, y0.w);
            V2[(d0 + 4) * KPF + kp] = splitp(x1.x, y1.x);
            V2[(d0 + 5) * KPF + kp] = splitp(x1.y, y1.y);
            V2[(d0 + 6) * KPF + kp] = splitp(x1.z, y1.z);
            V2[(d0 + 7) * KPF + kp] = splitp(x1.w, y1.w);
        }
        __syncthreads();

        // ---- S = Q K^T : warp tile 16 rows x 64 keys, bf16 x3 ----
        float s[8][4];
        #pragma unroll
        for (int nf = 0; nf < 8; nf++)
            #pragma unroll
            for (int e = 0; e < 4; e++) s[nf][e] = 0.f;

        #pragma unroll
        for (int step = 0; step < 4; step++) {
            const int ksp = step * 8;
            const uint2* q0p = Q2 + (rw + g) * QP2 + ksp;
            const uint2* q1p = Q2 + (rw + g + 8) * QP2 + ksp;
            uint2 qa = q0p[tg], qb = q1p[tg], qc = q0p[tg + 4], qd = q1p[tg + 4];
            uint32_t Ah[4] = {qa.x, qb.x, qc.x, qd.x};
            uint32_t Al[4] = {qa.y, qb.y, qc.y, qd.y};
            #pragma unroll
            for (int nf = 0; nf < 8; nf++) {
                const int key = nf * 8 + g;
                const int x0i = (ksp + tg) ^ ((nf & 1) * 4);
                uint2 b0 = K2[key * KPF + x0i];
                uint2 b1 = K2[key * KPF + (x0i ^ 4)];
                uint32_t Bh[2] = {b0.x, b1.x};
                uint32_t Bl[2] = {b0.y, b1.y};
                mma_bf16(s[nf], Ah, Bh);
                mma_bf16(s[nf], Ah, Bl);
                mma_bf16(s[nf], Al, Bh);
            }
        }

        // ---- online softmax: rows g (e0,e1) and g+8 (e2,e3) over 64 keys ----
        #pragma unroll
        for (int hh = 0; hh < 2; hh++) {
            const int e0 = 2 * hh;
            float mt = -1e30f;
            #pragma unroll
            for (int nf = 0; nf < 8; nf++)
                mt = fmaxf(mt, fmaxf(s[nf][e0], s[nf][e0 + 1]));
            mt = fmaxf(mt, __shfl_xor_sync(0xffffffffu, mt, 1));
            mt = fmaxf(mt, __shfl_xor_sync(0xffffffffu, mt, 2));
            const float mnew = fmaxf(mi[hh], mt);
            const float al   = fexp(mi[hh] - mnew);
            float ls = 0.f;
            #pragma unroll
            for (int nf = 0; nf < 8; nf++) {
                float e1 = fexp(s[nf][e0] - mnew);
                float e2 = fexp(s[nf][e0 + 1] - mnew);
                s[nf][e0] = e1; s[nf][e0 + 1] = e2;
                ls += e1 + e2;
            }
            ls += __shfl_xor_sync(0xffffffffu, ls, 1);
            ls += __shfl_xor_sync(0xffffffffu, ls, 2);
            li[hh] = li[hh] * al + ls;
            mi[hh] = mnew;
            #pragma unroll
            for (int nf = 0; nf < 8; nf++) {
                o[nf][e0]     *= al;
                o[nf][e0 + 1] *= al;
            }
        }

        // ---- O += P V : P packed register->register (no smem) ----
        #pragma unroll
        for (int j = 0; j < 4; j++) {
            uint2 p0 = splitp(s[2 * j][0],     s[2 * j][1]);
            uint2 p1 = splitp(s[2 * j][2],     s[2 * j][3]);
            uint2 p2 = splitp(s[2 * j + 1][0], s[2 * j + 1][1]);
            uint2 p3 = splitp(s[2 * j + 1][2], s[2 * j + 1][3]);
            uint32_t Ph[4] = {p0.x, p1.x, p2.x, p3.x};
            uint32_t Pl[4] = {p0.y, p1.y, p2.y, p3.y};
            #pragma unroll
            for (int nf = 0; nf < 8; nf++) {
                const int dd = nf * 8 + g;
                uint2 b0 = V2[dd * KPF + 8 * j + tg];
                uint2 b1 = V2[dd * KPF + 8 * j + tg + 4];
                uint32_t Bh[2] = {b0.x, b1.x};
                uint32_t Bl[2] = {b0.y, b1.y};
                mma_bf16(o[nf], Ph, Bh);
                mma_bf16(o[nf], Ph, Bl);
                mma_bf16(o[nf], Pl, Bh);
            }
        }
    }

    // ---- epilogue ----
    {
        const float i0 = 1.f / li[0];
        const float i1 = 1.f / li[1];
        const int r0 = b * N_T + q0 + rw + g;
        #pragma unroll
        for (int nf = 0; nf < 8; nf++) {
            const int c = h * D_HEAD + nf * 8 + 2 * tg;
            *(float2*)(g_ctx + (size_t)r0 * D_EMBED + c) =
                make_float2(o[nf][0] * i0, o[nf][1] * i0);
            *(float2*)(g_ctx + (size_t)(r0 + 8) * D_EMBED + c) =
                make_float2(o[nf][2] * i1, o[nf][3] * i1);
        }
    }
}

// ---------------------------------------------------------------------------
extern "C" void kernel_launch(void* const* d_in, const int* in_sizes, int n_in,
                              void* d_out, int out_size)
{
    (void)in_sizes; (void)n_in; (void)out_size;
    const float* x     = (const float*)d_in[0];
    const float* qkv_w = (const float*)d_in[1];
    const float* qkv_b = (const float*)d_in[2];
    const float* out_w = (const float*)d_in[3];
    const float* out_b = (const float*)d_in[4];
    float* out = (float*)d_out;

    cudaFuncSetAttribute(gemm_qkv_kernel,
                         cudaFuncAttributeMaxDynamicSharedMemorySize, GSMEM);
    cudaFuncSetAttribute(gemm_out_kernel,
                         cudaFuncAttributeMaxDynamicSharedMemorySize, GSMEM);
    cudaFuncSetAttribute(flash_kernel,
                         cudaFuncAttributeMaxDynamicSharedMemorySize, FL_SMEM);

    gemm_qkv_kernel<<<dim3(N_QKV / 128, M_TOT / 128), 256, GSMEM>>>(x, qkv_w, qkv_b);

    flash_kernel<<<dim3(N_T / 128, N_HEADS, N_B), 256, FL_SMEM>>>();

    gemm_out_kernel<<<dim3(D_EMBED / 128, M_TOT / 128), 256, GSMEM>>>(out_w, out_b, out);
}